// round 11
// baseline (speedup 1.0000x reference)
#include <cuda_runtime.h>
#include <cstdint>

#define CHAR_VOCAB 1001
#define EMB 256
#define H 192
#define G3 576   // 3*H
#define BATCH 32
#define SEQL 2048
#define NSPAN 512

// cluster split
#define JH 96            // outputs per CTA
#define KS 4             // K-split ways
#define KC 48            // K per slice
#define NTHR (JH * KS)   // 384 threads

// ---------------- scratch (no cudaMalloc allowed) ----------------
__device__ float g_proj[2][CHAR_VOCAB * G3];                 // 2 x 2.3 MB
__device__ float g_allh[(size_t)BATCH * SEQL * 2 * H];       // 100.7 MB

// ---------------- kernel 1: proj tables (unchanged, verified) ----------------
#define VB 16
__global__ void proj_kernel(const float* __restrict__ emb,
                            const float* __restrict__ w_ih_f, const float* __restrict__ b_ih_f,
                            const float* __restrict__ w_ih_b, const float* __restrict__ b_ih_b) {
    __shared__ float embs[VB][EMB];
    const int dir = blockIdx.y;
    const float* __restrict__ w  = dir ? w_ih_b : w_ih_f;
    const float* __restrict__ bi = dir ? b_ih_b : b_ih_f;
    const int v0 = blockIdx.x * VB;

    for (int i = threadIdx.x; i < VB * EMB; i += blockDim.x) {
        int v = v0 + i / EMB;
        embs[i / EMB][i % EMB] = (v < CHAR_VOCAB) ? emb[(size_t)v * EMB + (i % EMB)] : 0.f;
    }
    __syncthreads();

    const int g = threadIdx.x;  // 0..575
    float acc[VB];
#pragma unroll
    for (int i = 0; i < VB; i++) acc[i] = 0.f;

    const float4* __restrict__ w4 = (const float4*)(w + (size_t)g * EMB);
    for (int e4 = 0; e4 < EMB / 4; e4++) {
        float4 wv = w4[e4];
#pragma unroll
        for (int i = 0; i < VB; i++) {
            float4 ev = *(const float4*)&embs[i][e4 * 4];
            acc[i] = fmaf(wv.x, ev.x, fmaf(wv.y, ev.y, fmaf(wv.z, ev.z, fmaf(wv.w, ev.w, acc[i]))));
        }
    }
    float bb = bi[g];
#pragma unroll
    for (int i = 0; i < VB; i++) {
        int v = v0 + i;
        if (v < CHAR_VOCAB) g_proj[dir][(size_t)v * G3 + g] = acc[i] + bb;
    }
}

// ---------------- PTX helpers ----------------
__device__ __forceinline__ uint32_t smem_u32(const void* p) {
    uint32_t a;
    asm("{ .reg .u64 t; cvta.to.shared.u64 t, %1; cvt.u32.u64 %0, t; }" : "=r"(a) : "l"(p));
    return a;
}
__device__ __forceinline__ uint32_t mapa_u32(uint32_t laddr, uint32_t peer) {
    uint32_t r;
    asm("mapa.shared::cluster.u32 %0, %1, %2;" : "=r"(r) : "r"(laddr), "r"(peer));
    return r;
}
__device__ __forceinline__ void mbar_init(uint32_t a, uint32_t cnt) {
    asm volatile("mbarrier.init.shared.b64 [%0], %1;" :: "r"(a), "r"(cnt) : "memory");
}
__device__ __forceinline__ void mbar_arrive_local(uint32_t a) {
    asm volatile("mbarrier.arrive.release.cluster.shared::cta.b64 _, [%0];" :: "r"(a) : "memory");
}
__device__ __forceinline__ void mbar_arrive_remote(uint32_t ra) {
    asm volatile("mbarrier.arrive.release.cluster.shared::cluster.b64 _, [%0];" :: "r"(ra) : "memory");
}
__device__ __forceinline__ void st_remote_f32(uint32_t raddr, float v) {
    asm volatile("st.shared::cluster.b32 [%0], %1;" :: "r"(raddr), "r"(__float_as_uint(v)) : "memory");
}
__device__ __forceinline__ void mbar_wait_parity(uint32_t a, uint32_t parity) {
    uint32_t done;
    asm volatile("{\n\t.reg .pred p;\n\t"
        "mbarrier.try_wait.parity.acquire.cluster.shared::cta.b64 p, [%1], %2;\n\t"
        "selp.b32 %0, 1, 0, p;\n\t}"
        : "=r"(done) : "r"(a), "r"(parity) : "memory");
    while (!done) {
        asm volatile("{\n\t.reg .pred p;\n\t"
            "mbarrier.try_wait.parity.acquire.cluster.shared::cta.b64 p, [%1], %2, 0x989680;\n\t"
            "selp.b32 %0, 1, 0, p;\n\t}"
            : "=r"(done) : "r"(a), "r"(parity) : "memory");
    }
}
__device__ __forceinline__ void cluster_barrier() {
    asm volatile("barrier.cluster.arrive.aligned;" ::: "memory");
    asm volatile("barrier.cluster.wait.aligned;" ::: "memory");
}

// single-MUFU tanh; sigmoid(x) = 0.5 + 0.5*tanh(x/2)
__device__ __forceinline__ float tanh_apx(float x) {
    float y; asm("tanh.approx.f32 %0, %1;" : "=f"(y) : "f"(x)); return y;
}
__device__ __forceinline__ float sig_apx(float x) {
    return fmaf(0.5f, tanh_apx(0.5f * x), 0.5f);
}
__device__ __forceinline__ uint32_t bf16rn(float f) {
    uint32_t u = __float_as_uint(f);
    return (u + 0x7FFFu + ((u >> 16) & 1u)) >> 16;
}

// one dual-MAC on a packed bf16 pair (known-good regalloc form)
#define DOT2(a0, a1, w, hx, hy) { \
    float wl = __uint_as_float((w) << 16); \
    float wh = __uint_as_float((w) & 0xFFFF0000u); \
    a0 = fmaf(wl, (hx), a0); a1 = fmaf(wh, (hy), a1); }

// 3-gate dot over this thread's 48-element K slice
__device__ __forceinline__ void dot3(const float* __restrict__ hb,
                                     const uint32_t wv[3][24],
                                     float& sR, float& sZ, float& sN) {
    float aR0 = 0.f, aR1 = 0.f, aZ0 = 0.f, aZ1 = 0.f, aN0 = 0.f, aN1 = 0.f;
#pragma unroll
    for (int q = 0; q < 12; q++) {
        float4 h4 = *(const float4*)(hb + 4 * q);
        DOT2(aR0, aR1, wv[0][2 * q],     h4.x, h4.y);
        DOT2(aR0, aR1, wv[0][2 * q + 1], h4.z, h4.w);
        DOT2(aZ0, aZ1, wv[1][2 * q],     h4.x, h4.y);
        DOT2(aZ0, aZ1, wv[1][2 * q + 1], h4.z, h4.w);
        DOT2(aN0, aN1, wv[2][2 * q],     h4.x, h4.y);
        DOT2(aN0, aN1, wv[2][2 * q + 1], h4.z, h4.w);
    }
    sR = aR0 + aR1; sZ = aZ0 + aZ1; sN = aN0 + aN1;
}

// ---------------- kernel 2: clustered GRU, TWO batches per cluster ----------------
// cluster(2,1,1): rank r owns global j in [96r,96r+96) for BOTH batches.
// W_hh (shared by all batches of a direction) lives once in registers.
// Per iteration: [wait_b0, dot_b0, epi_b0] then [wait_b1, dot_b1, epi_b1] —
// each batch's DSMEM transit hides behind the other batch's compute.
__global__ void __launch_bounds__(NTHR, 1) __cluster_dims__(2, 1, 1)
gru_kernel(const int* __restrict__ char_ids,
           const float* __restrict__ w_hh_f, const float* __restrict__ b_hh_f,
           const float* __restrict__ w_hh_b, const float* __restrict__ b_hh_b) {
    __shared__ float hbuf[2][2][H];        // [batch][parity][H]
    __shared__ float part[2][2][9][JH];    // [batch][parity][(ks-1)*3+gate][jl]
    __shared__ int   ids_s[2][SEQL];
    __shared__ unsigned long long mb_rem[2];   // per batch, armed by peer (count 3)

    const int rank = blockIdx.x;
    const int dir  = blockIdx.y;
    const int bp   = blockIdx.z;           // batch pair 0..15
    const int b0   = 2 * bp, b1 = 2 * bp + 1;
    const float* __restrict__ whh = dir ? w_hh_b : w_hh_f;
    const float* __restrict__ bhh = dir ? b_hh_b : b_hh_f;
    const float* __restrict__ proj = g_proj[dir];

    const int tid = threadIdx.x;
    const int ks  = tid / JH;                 // 0..3 (uniform per warp)
    const int jl  = tid % JH;                 // 0..95
    const int jg  = rank * JH + jl;           // 0..191
    const int kslice = (ks + 2 * rank) & 3;   // ks<2 -> own half for BOTH ranks
    const bool own_half = (ks < 2);

    // ---- prologue ----
    if (tid == 0) {
#pragma unroll
        for (int p = 0; p < 2; p++) {
            mbar_init(smem_u32(&mb_rem[p]), 3);
            mbar_arrive_local(smem_u32(&mb_rem[p]));  // arm phase 0 (h=0 pre-set)
            mbar_arrive_local(smem_u32(&mb_rem[p]));
            mbar_arrive_local(smem_u32(&mb_rem[p]));
        }
    }
    ((float*)hbuf)[tid] = 0.f;
    ((float*)hbuf)[NTHR + tid] = 0.f;          // zero all 768 floats
    for (int t = tid; t < SEQL; t += NTHR) {
        ids_s[0][t] = char_ids[(size_t)b0 * SEQL + t];
        ids_s[1][t] = char_ids[(size_t)b1 * SEQL + t];
    }
    // W_hh slice -> registers, packed bf16 pairs (shared by both batches)
    uint32_t wv[3][24];
#pragma unroll
    for (int g = 0; g < 3; g++) {
        const float2* __restrict__ wr2 =
            (const float2*)(whh + ((size_t)(g * H + jg)) * H + kslice * KC);
#pragma unroll
        for (int q = 0; q < 24; q++) {
            float2 f = wr2[q];
            wv[g][q] = bf16rn(f.x) | (bf16rn(f.y) << 16);
        }
    }
    __syncthreads();
    cluster_barrier();   // barrier inits + zeroed hbuf visible cluster-wide

    const uint32_t rem_a0 = smem_u32(&mb_rem[0]);
    const uint32_t rem_a1 = smem_u32(&mb_rem[1]);
    const uint32_t peer = rank ^ 1;
    const uint32_t p_rem0 = mapa_u32(rem_a0, peer);
    const uint32_t p_rem1 = mapa_u32(rem_a1, peer);
    const uint32_t r_h00 = mapa_u32(smem_u32(&hbuf[0][0][jg]), peer);
    const uint32_t r_h01 = mapa_u32(smem_u32(&hbuf[0][1][jg]), peer);
    const uint32_t r_h10 = mapa_u32(smem_u32(&hbuf[1][0][jg]), peer);
    const uint32_t r_h11 = mapa_u32(smem_u32(&hbuf[1][1][jg]), peer);

    // ks0-only state (biases shared across batches — same direction)
    float bhr = 0.f, bhz = 0.f, bhn = 0.f;
    float h0 = 0.f, h1 = 0.f;
    float xr0 = 0.f, xz0 = 0.f, xn0 = 0.f, xr1 = 0.f, xz1 = 0.f, xn1 = 0.f;
    float* allh0 = g_allh + ((size_t)b0 * SEQL) * (2 * H) + dir * H + jg;
    float* allh1 = g_allh + ((size_t)b1 * SEQL) * (2 * H) + dir * H + jg;
    if (ks == 0) {
        bhr = bhh[jg]; bhz = bhh[H + jg]; bhn = bhh[2 * H + jg];
        int t0 = dir ? (SEQL - 1) : 0;
        const float* pa = proj + (size_t)ids_s[0][t0] * G3 + jg;
        xr0 = pa[0]; xz0 = pa[H]; xn0 = pa[2 * H];
        const float* pb = proj + (size_t)ids_s[1][t0] * G3 + jg;
        xr1 = pb[0]; xz1 = pb[H]; xn1 = pb[2 * H];
    }

#pragma unroll 1
    for (int s = 0; s < SEQL; s++) {
        const uint32_t par = (uint32_t)(s & 1);
        const int tcur = dir ? (SEQL - 1 - s) : s;
        const int sn = (s + 1 < SEQL) ? s + 1 : s;
        const int tn = dir ? (SEQL - 1 - sn) : sn;

        // ================= batch 0 =================
        if (own_half) {
            if (s > 0) asm volatile("bar.sync 2, 192;" ::: "memory");
        } else {
            mbar_wait_parity(rem_a0, par);
        }
        float xrN0 = 0.f, xzN0 = 0.f, xnN0 = 0.f;
        if (ks == 0) {
            const float* pn = proj + (size_t)ids_s[0][tn] * G3 + jg;
            xrN0 = __ldg(pn); xzN0 = __ldg(pn + H); xnN0 = __ldg(pn + 2 * H);
        }
        {
            float sR, sZ, sN;
            dot3(&hbuf[0][par][kslice * KC], wv, sR, sZ, sN);
            if (ks != 0) {
                part[0][par][(ks - 1) * 3 + 0][jl] = sR;
                part[0][par][(ks - 1) * 3 + 1][jl] = sZ;
                part[0][par][(ks - 1) * 3 + 2][jl] = sN;
            }
            __syncthreads();
            if (ks == 0) {
                float aR = sR + part[0][par][0][jl] + part[0][par][3][jl] + part[0][par][6][jl];
                float aZ = sZ + part[0][par][1][jl] + part[0][par][4][jl] + part[0][par][7][jl];
                float aN = sN + part[0][par][2][jl] + part[0][par][5][jl] + part[0][par][8][jl];
                float r = sig_apx(xr0 + bhr + aR);
                float z = sig_apx(xz0 + bhz + aZ);
                float n = tanh_apx(fmaf(r, aN + bhn, xn0));
                h0 = fmaf(z, h0 - n, n);
                hbuf[0][(s + 1) & 1][jg] = h0;
                st_remote_f32(par ? r_h00 : r_h01, h0);
                allh0[(size_t)tcur * (2 * H)] = h0;
                xr0 = xrN0; xz0 = xzN0; xn0 = xnN0;
                __syncwarp();
                if ((tid & 31) == 0) mbar_arrive_remote(p_rem0);
            }
        }

        // ================= batch 1 =================
        if (own_half) {
            if (s > 0) asm volatile("bar.sync 3, 192;" ::: "memory");
        } else {
            mbar_wait_parity(rem_a1, par);
        }
        float xrN1 = 0.f, xzN1 = 0.f, xnN1 = 0.f;
        if (ks == 0) {
            const float* pn = proj + (size_t)ids_s[1][tn] * G3 + jg;
            xrN1 = __ldg(pn); xzN1 = __ldg(pn + H); xnN1 = __ldg(pn + 2 * H);
        }
        {
            float sR, sZ, sN;
            dot3(&hbuf[1][par][kslice * KC], wv, sR, sZ, sN);
            if (ks != 0) {
                part[1][par][(ks - 1) * 3 + 0][jl] = sR;
                part[1][par][(ks - 1) * 3 + 1][jl] = sZ;
                part[1][par][(ks - 1) * 3 + 2][jl] = sN;
            }
            __syncthreads();
            if (ks == 0) {
                float aR = sR + part[1][par][0][jl] + part[1][par][3][jl] + part[1][par][6][jl];
                float aZ = sZ + part[1][par][1][jl] + part[1][par][4][jl] + part[1][par][7][jl];
                float aN = sN + part[1][par][2][jl] + part[1][par][5][jl] + part[1][par][8][jl];
                float r = sig_apx(xr1 + bhr + aR);
                float z = sig_apx(xz1 + bhz + aZ);
                float n = tanh_apx(fmaf(r, aN + bhn, xn1));
                h1 = fmaf(z, h1 - n, n);
                hbuf[1][(s + 1) & 1][jg] = h1;
                st_remote_f32(par ? r_h10 : r_h11, h1);
                allh1[(size_t)tcur * (2 * H)] = h1;
                xr1 = xrN1; xz1 = xzN1; xn1 = xnN1;
                __syncwarp();
                if ((tid & 31) == 0) mbar_arrive_remote(p_rem1);
            }
        }
    }

    cluster_barrier();   // no CTA exits while peer may still write into it
}

// ---------------- alignment no-op (puts gru_kernel at absolute launch idx 3) ----------------
__global__ void nop_kernel() {}

// ---------------- kernel 3: gather (unchanged, verified) ----------------
__global__ void gather_kernel(const int* __restrict__ start_ids,
                              const int* __restrict__ end_ids,
                              float* __restrict__ out) {
    const int s = blockIdx.x, b = blockIdx.y;
    const int tid = threadIdx.x;  // 192 threads, 1 float4 each
    const int st = start_ids[(size_t)b * NSPAN + s];
    const int en = end_ids[(size_t)b * NSPAN + s];
    float4* orow = (float4*)(out + ((size_t)b * NSPAN + s) * 768);
    const float4* allh = (const float4*)g_allh;
    if (tid < 96) {
        orow[tid] = allh[((size_t)b * SEQL + st) * 96 + tid];
    } else {
        orow[tid] = allh[((size_t)b * SEQL + en) * 96 + (tid - 96)];
    }
}

// ---------------- launch ----------------
extern "C" void kernel_launch(void* const* d_in, const int* in_sizes, int n_in,
                              void* d_out, int out_size) {
    const int*   char_ids  = (const int*)d_in[0];
    const int*   start_ids = (const int*)d_in[1];
    const int*   end_ids   = (const int*)d_in[2];
    const float* emb       = (const float*)d_in[3];
    const float* w_ih_f    = (const float*)d_in[4];
    const float* w_hh_f    = (const float*)d_in[5];
    const float* b_ih_f    = (const float*)d_in[6];
    const float* b_hh_f    = (const float*)d_in[7];
    const float* w_ih_b    = (const float*)d_in[8];
    const float* w_hh_b    = (const float*)d_in[9];
    const float* b_ih_b    = (const float*)d_in[10];
    const float* b_hh_b    = (const float*)d_in[11];
    float* out = (float*)d_out;

    // launch order chosen so absolute launch index 3 (the ncu-profiled one) = gru
    nop_kernel<<<1, 32>>>();

    // 1) projection tables: proj[d] = emb @ w_ih_d^T + b_ih_d  [1001, 576]
    proj_kernel<<<dim3((CHAR_VOCAB + VB - 1) / VB, 2), G3>>>(emb, w_ih_f, b_ih_f, w_ih_b, b_ih_b);

    nop_kernel<<<1, 32>>>();

    // 2) clustered bidirectional GRU: 2 batches per 2-CTA cluster, 32 clusters
    gru_kernel<<<dim3(2, 2, BATCH / 2), NTHR>>>(char_ids, w_hh_f, b_hh_f, w_hh_b, b_hh_b);

    // 3) gather start/end hidden states into output [32, 512, 768]
    gather_kernel<<<dim3(NSPAN, BATCH), 192>>>(start_ids, end_ids, out);
}